// round 9
// baseline (speedup 1.0000x reference)
#include <cuda_runtime.h>
#include <math.h>
#include <stdint.h>

#define Nn 4096
#define Mm 4096
#define LAMDA 0.01f
#define STOP_THR 1e-7
#define MAX_ITER 100
#define NB 128
#define NT 512
#define NW 16   // warps per block
#define S2 70   // smem row stride (floats) — MUST be even (8B smem accesses)

typedef unsigned long long ull;

// ---------------- device globals (no cudaMalloc allowed) ----------------
__device__ float  g_K[(size_t)Nn * Mm];            // 64 MB fp32 kernel matrix
__device__ unsigned g_Khu[(size_t)Nn * (Mm / 2)];  // 32 MB bf16 shadow (pairs)
__device__ float  g_a[2][Nn];
__device__ float  g_b[2][Mm];
__device__ double g_bdisp[NB];
__device__ double g_bcost[NB];
__device__ unsigned g_bar_cnt;                     // monotonic arrive counter

// ---------------- fast exp: FFMA-only (no MUFU), rel err ~1e-7 ----------
__device__ __forceinline__ float fexp(float xx) {
    float t  = fmaf(xx, 1.4426950408889634f, 12582912.0f);
    int   n  = __float_as_int(t) - 0x4B400000;
    float fn = t - 12582912.0f;
    float r  = fmaf(fn, -0.693145751953125f, xx);
    r        = fmaf(fn, -1.42860677e-6f, r);
    float p  = 1.3888890e-3f;
    p = fmaf(p, r, 8.3333338e-3f);
    p = fmaf(p, r, 4.1666668e-2f);
    p = fmaf(p, r, 1.6666667e-1f);
    p = fmaf(p, r, 5.0000000e-1f);
    p = fmaf(p, r, 1.0f);
    p = fmaf(p, r, 1.0f);
    return __int_as_float(__float_as_int(p) + (n << 23));
}

#define FMA2(d, a, b) \
    asm("fma.rn.f32x2 %0, %1, %2, %0;" : "+l"(d) : "l"(a), "l"(b))
#define MUL2(d, a, b) \
    asm("mul.rn.f32x2 %0, %1, %2;" : "=l"(d) : "l"(a), "l"(b))
#define UNPACK2(lo, hi, v) \
    asm("mov.b64 {%0, %1}, %2;" : "=f"(lo), "=f"(hi) : "l"(v))
#define PACKF2(d, lo, hi) \
    asm("mov.b64 %0, {%1, %2};" : "=l"(d) : "f"(lo), "f"(hi))
#define CVT_BF16X2(r, hi, lo) \
    asm("cvt.rn.satfinite.bf16x2.f32 %0, %1, %2;" : "=r"(r) : "f"(hi), "f"(lo))

// bf16 pair (packed in uint) -> f32x2 (bf16 is the top half of f32)
__device__ __forceinline__ ull bf2_to_f32x2(unsigned v) {
    float lo = __uint_as_float(v << 16);
    float hi = __uint_as_float(v & 0xffff0000u);
    ull d; PACKF2(d, lo, hi);
    return d;
}

// ------------- cheap acquire/release grid barrier (no MEMBAR.GPU) -------
__device__ __forceinline__ void red_rel_add1(unsigned* p) {
    asm volatile("red.release.gpu.global.add.u32 [%0], 1;" :: "l"(p) : "memory");
}
__device__ __forceinline__ unsigned ld_acq(unsigned* p) {
    unsigned v;
    asm volatile("ld.acquire.gpu.global.u32 %0, [%1];" : "=r"(v) : "l"(p) : "memory");
    return v;
}
__device__ __forceinline__ void gbar(unsigned target) {
    __syncthreads();
    if (threadIdx.x == 0) {
        red_rel_add1(&g_bar_cnt);
        while ((int)(ld_acq(&g_bar_cnt) - target) < 0) { }
    }
    __syncthreads();
}

// ---------------- fused persistent kernel ----------------
__global__ void __launch_bounds__(NT, 1)
fused_kernel(const float* __restrict__ x, const float* __restrict__ y,
             const float* __restrict__ mu, const float* __restrict__ nu,
             float* __restrict__ out) {
    extern __shared__ float sm[];
    __shared__ float  sred[NW][33];
    __shared__ double sRow[32];
    __shared__ double sDS1[32];
    __shared__ double sDisp;

    const int tid = threadIdx.x, blk = blockIdx.x;
    const int warp = tid >> 5, lane = tid & 31;
    const unsigned FULL = 0xffffffffu;
    const unsigned base = __ldcg(&g_bar_cnt);
    unsigned gen = 0;

    float* Pout = out + 1;                    // rows at byte phase 4 (mod 16)
    float* Cmat = out + 1 + (size_t)Nn * Mm;  // same phase

    if (tid < 32) {
        g_a[0][blk * 32 + tid] = 1.0f / (float)Nn;
        g_b[0][blk * 32 + tid] = 1.0f;
    }

    // ================= CK phase: 16 tiles of 128x64 per block ============
    // Only fp32 K stored here.  C reconstructed later as -100*ln(K).
    {
        float* XS = sm;                 // [128][S2]
        float* YS = sm + 128 * S2;      // [64][S2]
        float* xn = YS + 64 * S2;       // [128]
        float* yn = xn + 128;           // [64]
        const int i_tile = blk >> 2, jb = (blk & 3) * 16;
        const int i0 = i_tile * 128;

        for (int t = tid; t < 4096; t += NT) {
            int r = t >> 5, c = t & 31;
            float2 v = __ldg((const float2*)(x + (size_t)(i0 + r) * 64) + c);
            *(float2*)(XS + r * S2 + 2 * c) = v;
        }
        __syncthreads();
        if (tid < 128) {
            float s = 0.f;
            #pragma unroll
            for (int k = 0; k < 64; k++) { float v = XS[tid * S2 + k]; s = fmaf(v, v, s); }
            xn[tid] = s;
        }

        const int tx = tid & 15, ty = tid >> 4, iy = ty * 4;
        for (int s = 0; s < 16; s++) {
            const int j0 = (jb + s) * 64;
            __syncthreads();   // previous tile fully consumed
            for (int t = tid; t < 2048; t += NT) {
                int r = t >> 5, c = t & 31;
                float2 v = __ldg((const float2*)(y + (size_t)(j0 + r) * 64) + c);
                *(float2*)(YS + r * S2 + 2 * c) = v;
            }
            __syncthreads();
            if (tid < 64) {
                float sv = 0.f;
                #pragma unroll
                for (int k = 0; k < 64; k++) { float v = YS[tid * S2 + k]; sv = fmaf(v, v, sv); }
                yn[tid] = sv;
            }
            __syncthreads();

            ull acc[4][4];
            #pragma unroll
            for (int u = 0; u < 4; u++)
                #pragma unroll
                for (int w = 0; w < 4; w++) acc[u][w] = 0ULL;

            #pragma unroll 4
            for (int kp = 0; kp < 32; kp++) {
                const int k = kp * 2;
                ull xp[4], yp[4];
                #pragma unroll
                for (int u = 0; u < 4; u++)
                    xp[u] = *(const ull*)(XS + (iy + u) * S2 + k);
                #pragma unroll
                for (int w = 0; w < 4; w++)
                    yp[w] = *(const ull*)(YS + (tx + 16 * w) * S2 + k);
                #pragma unroll
                for (int u = 0; u < 4; u++)
                    #pragma unroll
                    for (int w = 0; w < 4; w++)
                        FMA2(acc[u][w], xp[u], yp[w]);
            }

            #pragma unroll
            for (int u = 0; u < 4; u++) {
                const int i = i0 + iy + u;
                const float xni = xn[iy + u];
                #pragma unroll
                for (int w = 0; w < 4; w++) {
                    const int jl = tx + 16 * w;
                    float lo, hi;
                    UNPACK2(lo, hi, acc[u][w]);
                    float Cv = xni + yn[jl] - 2.0f * (lo + hi);
                    g_K[(size_t)i * Mm + j0 + jl] = fexp(-LAMDA * Cv);
                }
            }
        }
    }
    gbar(base + (++gen) * NB);

    // ================= repack K -> bf16 shadow (vectorized, L2 resident) ==
    {
        const float4* K4 = (const float4*)g_K;
        uint2* Kh2 = (uint2*)g_Khu;
        const int gid = blk * NT + tid;
        for (size_t q = gid; q < (size_t)Nn * Mm / 4; q += (size_t)NB * NT) {
            float4 v = K4[q];
            uint2 o;
            CVT_BF16X2(o.x, v.y, v.x);
            CVT_BF16X2(o.y, v.w, v.z);
            Kh2[q] = o;
        }
    }
    gbar(base + (++gen) * NB);

    // ================= Sinkhorn loop (bf16 K) =============================
    float* sA = sm;          // 16 KB
    float* sB = sm + Mm;     // 16 KB
    int fpar = 0;

    for (int it = 0; it < MAX_ITER; ++it) {
        const int cur = it & 1, nxt = cur ^ 1;

        // ---- Phase A: b[nxt] = nu / (K^T a[cur]); block owns cols [blk*32,+32)
        for (int i = tid; i < Nn; i += NT) sA[i] = __ldcg(&g_a[cur][i]);
        __syncthreads();
        {
            const int p = lane & 15, rh = lane >> 4;     // col pair, row half
            const unsigned* Kc = g_Khu + (size_t)blk * 16 + p;
            ull acc2[8];
            #pragma unroll
            for (int u = 0; u < 8; u++) acc2[u] = 0ULL;
            for (int ib = 0; ib < Nn; ib += 256) {
                #pragma unroll
                for (int u = 0; u < 8; u++) {
                    const int i = ib + warp * 16 + 2 * u + rh;
                    ull kp = bf2_to_f32x2(Kc[(size_t)i * (Mm / 2)]);
                    float a = sA[i];
                    ull aa; PACKF2(aa, a, a);
                    FMA2(acc2[u], kp, aa);
                }
            }
            float sx = 0.f, sy = 0.f;
            #pragma unroll
            for (int u = 0; u < 8; u++) {
                float lo, hi; UNPACK2(lo, hi, acc2[u]);
                sx += lo; sy += hi;
            }
            float ox = __shfl_down_sync(FULL, sx, 16);
            float oy = __shfl_down_sync(FULL, sy, 16);
            if (rh == 0) {
                sred[warp][2 * p]     = sx + ox;
                sred[warp][2 * p + 1] = sy + oy;
            }
        }
        __syncthreads();
        if (warp == 0) {
            float s = 0.f;
            #pragma unroll
            for (int w = 0; w < NW; ++w) s += sred[w][lane];
            int j = blk * 32 + lane;
            g_b[nxt][j] = __ldg(&nu[j]) / s;
        }
        gbar(base + (++gen) * NB);

        // ---- Phase B: a[nxt] = mu/(K b_new), fused f32x2 disp GEMVs
        for (int i = tid; i < Mm; i += NT) sA[i] = __ldcg(&g_b[nxt][i]);
        for (int i = tid; i < Mm; i += NT) sB[i] = __ldcg(&g_b[cur][i]);
        __syncthreads();
        #pragma unroll
        for (int rr = 0; rr < 2; ++rr) {
            const int i = blk * 32 + warp * 2 + rr;
            const uint2* Kr2 = (const uint2*)(g_Khu + (size_t)i * (Mm / 2));
            const ull* A2 = (const ull*)sA;
            const ull* B2 = (const ull*)sB;
            ull t = 0ULL, s1 = 0ULL, s2 = 0ULL;
            #pragma unroll 4
            for (int q = lane; q < Mm / 4; q += 32) {
                uint2 v = Kr2[q];
                ull k01 = bf2_to_f32x2(v.x);
                ull k23 = bf2_to_f32x2(v.y);
                ull bn0 = A2[2 * q], bn1 = A2[2 * q + 1];
                ull be0 = B2[2 * q], be1 = B2[2 * q + 1];
                ull k2, tmp;
                MUL2(k2, k01, k01);
                FMA2(t, k01, bn0);
                MUL2(tmp, k2, bn0);
                FMA2(s1, tmp, bn0);
                FMA2(s2, tmp, be0);
                MUL2(k2, k23, k23);
                FMA2(t, k23, bn1);
                MUL2(tmp, k2, bn1);
                FMA2(s1, tmp, bn1);
                FMA2(s2, tmp, be1);
            }
            float tl, th, l1, h1, l2, h2;
            UNPACK2(tl, th, t);  UNPACK2(l1, h1, s1);  UNPACK2(l2, h2, s2);
            float tf = tl + th, s1f = l1 + h1, s2f = l2 + h2;
            #pragma unroll
            for (int off = 16; off; off >>= 1) {
                tf  += __shfl_down_sync(FULL, tf,  off);
                s1f += __shfl_down_sync(FULL, s1f, off);
                s2f += __shfl_down_sync(FULL, s2f, off);
            }
            if (lane == 0) {
                float an = __ldg(&mu[i]) / tf;
                g_a[nxt][i] = an;
                double dan = (double)an;
                double dao = (double)__ldcg(&g_a[cur][i]);
                double dS1 = dan * dan * (double)s1f;
                double d = (it == 0)
                    ? dS1
                    : dS1 - 2.0 * dan * dao * (double)s2f + sDS1[warp * 2 + rr];
                sDS1[warp * 2 + rr] = dS1;
                sRow[warp * 2 + rr] = d;
            }
        }
        __syncthreads();
        if (tid == 0) {
            double s = 0.0;
            #pragma unroll
            for (int q = 0; q < 32; ++q) s += sRow[q];
            g_bdisp[blk] = s;
        }
        gbar(base + (++gen) * NB);

        if (warp == 0) {
            double sd = __ldcg(&g_bdisp[lane])      + __ldcg(&g_bdisp[lane + 32])
                      + __ldcg(&g_bdisp[lane + 64]) + __ldcg(&g_bdisp[lane + 96]);
            #pragma unroll
            for (int off = 16; off; off >>= 1)
                sd += __shfl_down_sync(FULL, sd, off);
            if (lane == 0) sDisp = sd;
        }
        __syncthreads();
        fpar = nxt;
        if (sDisp <= STOP_THR) break;
    }

    // ================= epilogue: P = a*K*b^T, C = -100*ln(K), cost ========
    // fp32 K path.  P/C rows at byte phase 4 (mod 16): aligned quads at j=3+4q.
    __syncthreads();
    for (int i = tid; i < Mm; i += NT) sA[i] = __ldcg(&g_b[fpar][i]);
    __syncthreads();
    for (int m = tid; m < Mm - 3; m += NT) sB[m] = sA[m + 3];   // shifted copy
    __syncthreads();
    const float4* Bsh4 = (const float4*)sB;

    #pragma unroll
    for (int rr = 0; rr < 2; ++rr) {
        const int i = blk * 32 + warp * 2 + rr;
        const float ai = __ldcg(&g_a[fpar][i]);
        const float*  Kr = g_K + (size_t)i * Mm;
        const float4* K4 = (const float4*)Kr;
        float* Pr = Pout + (size_t)i * Mm;
        float* Cr = Cmat + (size_t)i * Mm;
        float csum = 0.f;

        if (lane < 3) {                  // head: j = 0,1,2
            float k = Kr[lane];
            float p = ai * k * sA[lane];
            float c = -69.31471805599453f * __log2f(k);
            __stcs(Pr + lane, p);
            __stcs(Cr + lane, c);
            csum = fmaf(p, c, csum);
        }

        float4 curr = K4[lane];
        for (int s = 0; s < 32; s++) {
            const int q = lane + 32 * s;
            const int nidx = (s < 31) ? (lane + 32 * (s + 1)) : lane;
            float4 newq = K4[nidx];
            float nx = __shfl_down_sync(FULL, curr.x, 1);
            float ny = __shfl_down_sync(FULL, curr.y, 1);
            float nz = __shfl_down_sync(FULL, curr.z, 1);
            float bx = __shfl_sync(FULL, newq.x, 0);
            float by = __shfl_sync(FULL, newq.y, 0);
            float bz = __shfl_sync(FULL, newq.z, 0);
            if (lane == 31) { nx = bx; ny = by; nz = bz; }

            if (q <= 1022) {
                const int jst = 4 * q + 3;
                float k0 = curr.w, k1 = nx, k2 = ny, k3 = nz;
                float4 bq = Bsh4[q];
                float p0 = ai * k0 * bq.x, p1 = ai * k1 * bq.y;
                float p2 = ai * k2 * bq.z, p3 = ai * k3 * bq.w;
                float c0 = -69.31471805599453f * __log2f(k0);
                float c1 = -69.31471805599453f * __log2f(k1);
                float c2 = -69.31471805599453f * __log2f(k2);
                float c3 = -69.31471805599453f * __log2f(k3);
                float4 pq; pq.x = p0; pq.y = p1; pq.z = p2; pq.w = p3;
                float4 cq; cq.x = c0; cq.y = c1; cq.z = c2; cq.w = c3;
                __stcs((float4*)(Pr + jst), pq);
                __stcs((float4*)(Cr + jst), cq);
                csum = fmaf(p0, c0, csum); csum = fmaf(p1, c1, csum);
                csum = fmaf(p2, c2, csum); csum = fmaf(p3, c3, csum);
            }
            if (s == 31 && lane == 31) {  // tail j = 4095
                float k = curr.w;
                float p = ai * k * sA[4095];
                float c = -69.31471805599453f * __log2f(k);
                __stcs(Pr + 4095, p);
                __stcs(Cr + 4095, c);
                csum = fmaf(p, c, csum);
            }
            curr = newq;
        }

        #pragma unroll
        for (int off = 16; off; off >>= 1)
            csum += __shfl_down_sync(FULL, csum, off);
        if (lane == 0) sRow[warp * 2 + rr] = (double)csum;
    }
    __syncthreads();
    if (tid == 0) {
        double s = 0.0;
        #pragma unroll
        for (int q = 0; q < 32; ++q) s += sRow[q];
        g_bcost[blk] = s;
    }
    gbar(base + (++gen) * NB);
    if (blk == 0 && warp == 0) {
        double sc = __ldcg(&g_bcost[lane])      + __ldcg(&g_bcost[lane + 32])
                  + __ldcg(&g_bcost[lane + 64]) + __ldcg(&g_bcost[lane + 96]);
        #pragma unroll
        for (int off = 16; off; off >>= 1)
            sc += __shfl_down_sync(FULL, sc, off);
        if (lane == 0) out[0] = (float)sc;
    }
}

// ---------------- launch ----------------
extern "C" void kernel_launch(void* const* d_in, const int* in_sizes, int n_in,
                              void* d_out, int out_size) {
    const float* x  = (const float*)d_in[0];   // [4096,64]
    const float* y  = (const float*)d_in[1];   // [4096,64]
    const float* mu = (const float*)d_in[2];   // [4096]
    const float* nu = (const float*)d_in[3];   // [4096]
    float* out = (float*)d_out;                // [1 + N*M + N*M] = cost | P | C

    const int smem = (128 * S2 + 64 * S2 + 128 + 64) * (int)sizeof(float);
    cudaFuncSetAttribute(fused_kernel, cudaFuncAttributeMaxDynamicSharedMemorySize, smem);
    fused_kernel<<<NB, NT, smem>>>(x, y, mu, nu, out);
}

// round 10
// speedup vs baseline: 1.2218x; 1.2218x over previous
#include <cuda_runtime.h>
#include <math.h>
#include <stdint.h>

#define Nn 4096
#define Mm 4096
#define LAMDA 0.01f
#define STOP_THR 1e-7
#define MAX_ITER 100
#define NB 128
#define NT 512
#define NW 16   // warps per block
#define S2 70   // smem row stride (floats) — MUST be even (8B smem accesses)

typedef unsigned long long ull;

// ---------------- device globals (no cudaMalloc allowed) ----------------
__device__ float  g_K[(size_t)Nn * Mm];   // 64 MB fp32 kernel matrix
__device__ float  g_a[2][Nn];
__device__ float  g_b[2][Mm];
__device__ double g_bdisp[NB];
__device__ double g_bcost[NB];
__device__ unsigned g_bar_cnt;            // monotonic arrive counter

// ---------------- fast exp: FFMA-only (no MUFU), rel err ~1e-7 ----------
__device__ __forceinline__ float fexp(float xx) {
    float t  = fmaf(xx, 1.4426950408889634f, 12582912.0f);
    int   n  = __float_as_int(t) - 0x4B400000;
    float fn = t - 12582912.0f;
    float r  = fmaf(fn, -0.693145751953125f, xx);
    r        = fmaf(fn, -1.42860677e-6f, r);
    float p  = 1.3888890e-3f;
    p = fmaf(p, r, 8.3333338e-3f);
    p = fmaf(p, r, 4.1666668e-2f);
    p = fmaf(p, r, 1.6666667e-1f);
    p = fmaf(p, r, 5.0000000e-1f);
    p = fmaf(p, r, 1.0f);
    p = fmaf(p, r, 1.0f);
    return __int_as_float(__float_as_int(p) + (n << 23));
}

#define FMA2(d, a, b) \
    asm("fma.rn.f32x2 %0, %1, %2, %0;" : "+l"(d) : "l"(a), "l"(b))
#define MUL2(d, a, b) \
    asm("mul.rn.f32x2 %0, %1, %2;" : "=l"(d) : "l"(a), "l"(b))
#define UNPACK2(lo, hi, v) \
    asm("mov.b64 {%0, %1}, %2;" : "=f"(lo), "=f"(hi) : "l"(v))

// ------------- cheap acquire/release grid barrier (no MEMBAR.GPU) -------
__device__ __forceinline__ void red_rel_add1(unsigned* p) {
    asm volatile("red.release.gpu.global.add.u32 [%0], 1;" :: "l"(p) : "memory");
}
__device__ __forceinline__ unsigned ld_acq(unsigned* p) {
    unsigned v;
    asm volatile("ld.acquire.gpu.global.u32 %0, [%1];" : "=r"(v) : "l"(p) : "memory");
    return v;
}
__device__ __forceinline__ void gbar(unsigned target) {
    __syncthreads();
    if (threadIdx.x == 0) {
        red_rel_add1(&g_bar_cnt);
        while ((int)(ld_acq(&g_bar_cnt) - target) < 0) { }
    }
    __syncthreads();
}

// ---------------- fused persistent kernel ----------------
__global__ void __launch_bounds__(NT, 1)
fused_kernel(const float* __restrict__ x, const float* __restrict__ y,
             const float* __restrict__ mu, const float* __restrict__ nu,
             float* __restrict__ out) {
    extern __shared__ float sm[];
    __shared__ float  sred[NW][33];
    __shared__ double sRow[32];
    __shared__ double sDS1[32];
    __shared__ double sDisp;

    const int tid = threadIdx.x, blk = blockIdx.x;
    const int warp = tid >> 5, lane = tid & 31;
    const unsigned FULL = 0xffffffffu;
    const unsigned base = __ldcg(&g_bar_cnt);
    unsigned gen = 0;

    float* Pout = out + 1;                    // rows at byte phase 4 (mod 16)
    float* Cmat = out + 1 + (size_t)Nn * Mm;  // same phase

    if (tid < 32) {
        g_a[0][blk * 32 + tid] = 1.0f / (float)Nn;
        g_b[0][blk * 32 + tid] = 1.0f;
    }

    // ================= CK phase: 16 tiles of 128x64 per block ============
    // Only K = exp(-lamda*C) stored.  C reconstructed later as -100*ln(K).
    {
        float* XS = sm;                 // [128][S2]
        float* YS = sm + 128 * S2;      // [64][S2]
        float* xn = YS + 64 * S2;       // [128]
        float* yn = xn + 128;           // [64]
        const int i_tile = blk >> 2, jb = (blk & 3) * 16;
        const int i0 = i_tile * 128;

        for (int t = tid; t < 4096; t += NT) {
            int r = t >> 5, c = t & 31;
            float2 v = __ldg((const float2*)(x + (size_t)(i0 + r) * 64) + c);
            *(float2*)(XS + r * S2 + 2 * c) = v;
        }
        __syncthreads();
        if (tid < 128) {
            float s = 0.f;
            #pragma unroll
            for (int k = 0; k < 64; k++) { float v = XS[tid * S2 + k]; s = fmaf(v, v, s); }
            xn[tid] = s;
        }

        const int tx = tid & 15, ty = tid >> 4, iy = ty * 4;
        for (int s = 0; s < 16; s++) {
            const int j0 = (jb + s) * 64;
            __syncthreads();   // previous tile fully consumed
            for (int t = tid; t < 2048; t += NT) {
                int r = t >> 5, c = t & 31;
                float2 v = __ldg((const float2*)(y + (size_t)(j0 + r) * 64) + c);
                *(float2*)(YS + r * S2 + 2 * c) = v;
            }
            __syncthreads();
            if (tid < 64) {
                float sv = 0.f;
                #pragma unroll
                for (int k = 0; k < 64; k++) { float v = YS[tid * S2 + k]; sv = fmaf(v, v, sv); }
                yn[tid] = sv;
            }
            __syncthreads();

            ull acc[4][4];
            #pragma unroll
            for (int u = 0; u < 4; u++)
                #pragma unroll
                for (int w = 0; w < 4; w++) acc[u][w] = 0ULL;

            #pragma unroll 4
            for (int kp = 0; kp < 32; kp++) {
                const int k = kp * 2;
                ull xp[4], yp[4];
                #pragma unroll
                for (int u = 0; u < 4; u++)
                    xp[u] = *(const ull*)(XS + (iy + u) * S2 + k);
                #pragma unroll
                for (int w = 0; w < 4; w++)
                    yp[w] = *(const ull*)(YS + (tx + 16 * w) * S2 + k);
                #pragma unroll
                for (int u = 0; u < 4; u++)
                    #pragma unroll
                    for (int w = 0; w < 4; w++)
                        FMA2(acc[u][w], xp[u], yp[w]);
            }

            #pragma unroll
            for (int u = 0; u < 4; u++) {
                const int i = i0 + iy + u;
                const float xni = xn[iy + u];
                #pragma unroll
                for (int w = 0; w < 4; w++) {
                    const int jl = tx + 16 * w;
                    float lo, hi;
                    UNPACK2(lo, hi, acc[u][w]);
                    float Cv = xni + yn[jl] - 2.0f * (lo + hi);
                    g_K[(size_t)i * Mm + j0 + jl] = fexp(-LAMDA * Cv);
                }
            }
        }
    }
    gbar(base + (++gen) * NB);

    // ================= Sinkhorn loop ======================================
    float* sA = sm;          // 16 KB
    float* sB = sm + Mm;     // 16 KB
    int fpar = 0;

    for (int it = 0; it < MAX_ITER; ++it) {
        const int cur = it & 1, nxt = cur ^ 1;

        // ---- Phase A: b[nxt] = nu / (K^T a[cur]); block owns cols [blk*32,+32)
        // 16 independent accumulators -> 16 LDG in flight per warp.
        for (int i = tid; i < Nn; i += NT) sA[i] = __ldcg(&g_a[cur][i]);
        __syncthreads();
        {
            const int j = blk * 32 + lane;
            const float* Kc = g_K + j;
            float acc[16];
            #pragma unroll
            for (int u = 0; u < 16; u++) acc[u] = 0.f;
            for (int ib = 0; ib < Nn; ib += 256) {
                #pragma unroll
                for (int u = 0; u < 16; u++) {
                    const int i = ib + warp + 16 * u;
                    acc[u] = fmaf(Kc[(size_t)i * Mm], sA[i], acc[u]);
                }
            }
            float s0 = ((acc[0] + acc[1])   + (acc[2] + acc[3]))
                     + ((acc[4] + acc[5])   + (acc[6] + acc[7]));
            float s1 = ((acc[8] + acc[9])   + (acc[10] + acc[11]))
                     + ((acc[12] + acc[13]) + (acc[14] + acc[15]));
            sred[warp][lane] = s0 + s1;
        }
        __syncthreads();
        if (warp == 0) {
            float s = 0.f;
            #pragma unroll
            for (int w = 0; w < NW; ++w) s += sred[w][lane];
            int j = blk * 32 + lane;
            g_b[nxt][j] = __ldg(&nu[j]) / s;
        }
        gbar(base + (++gen) * NB);

        // ---- Phase B: a[nxt] = mu/(K b_new) + fused disp GEMVs
        // Both owned rows processed in ONE loop (latency overlapped).
        for (int i = tid; i < Mm; i += NT) sA[i] = __ldcg(&g_b[nxt][i]);
        for (int i = tid; i < Mm; i += NT) sB[i] = __ldcg(&g_b[cur][i]);
        __syncthreads();
        {
            const int i0r = blk * 32 + warp * 2;
            const ull* K2a = (const ull*)(g_K + (size_t)i0r * Mm);
            const ull* K2b = (const ull*)(g_K + (size_t)(i0r + 1) * Mm);
            const ull* A2 = (const ull*)sA;
            const ull* B2 = (const ull*)sB;
            ull ta = 0ULL, s1a = 0ULL, s2a = 0ULL;
            ull tb = 0ULL, s1b = 0ULL, s2b = 0ULL;
            #pragma unroll 4
            for (int j = lane; j < Mm / 2; j += 32) {
                ull ka = K2a[j], kb = K2b[j];
                ull bn = A2[j], be = B2[j];
                ull k2, tmp;
                MUL2(k2, ka, ka);
                FMA2(ta, ka, bn);
                MUL2(tmp, k2, bn);
                FMA2(s1a, tmp, bn);
                FMA2(s2a, tmp, be);
                MUL2(k2, kb, kb);
                FMA2(tb, kb, bn);
                MUL2(tmp, k2, bn);
                FMA2(s1b, tmp, bn);
                FMA2(s2b, tmp, be);
            }
            float l, h;
            UNPACK2(l, h, ta);  float tfa = l + h;
            UNPACK2(l, h, s1a); float s1fa = l + h;
            UNPACK2(l, h, s2a); float s2fa = l + h;
            UNPACK2(l, h, tb);  float tfb = l + h;
            UNPACK2(l, h, s1b); float s1fb = l + h;
            UNPACK2(l, h, s2b); float s2fb = l + h;
            #pragma unroll
            for (int off = 16; off; off >>= 1) {
                tfa  += __shfl_down_sync(FULL, tfa,  off);
                s1fa += __shfl_down_sync(FULL, s1fa, off);
                s2fa += __shfl_down_sync(FULL, s2fa, off);
                tfb  += __shfl_down_sync(FULL, tfb,  off);
                s1fb += __shfl_down_sync(FULL, s1fb, off);
                s2fb += __shfl_down_sync(FULL, s2fb, off);
            }
            if (lane == 0) {
                // row A
                {
                    const int i = i0r;
                    float an = __ldg(&mu[i]) / tfa;
                    g_a[nxt][i] = an;
                    double dan = (double)an;
                    double dao = (double)__ldcg(&g_a[cur][i]);
                    double dS1 = dan * dan * (double)s1fa;
                    double d = (it == 0)
                        ? dS1
                        : dS1 - 2.0 * dan * dao * (double)s2fa + sDS1[warp * 2];
                    sDS1[warp * 2] = dS1;
                    sRow[warp * 2] = d;
                }
                // row B
                {
                    const int i = i0r + 1;
                    float an = __ldg(&mu[i]) / tfb;
                    g_a[nxt][i] = an;
                    double dan = (double)an;
                    double dao = (double)__ldcg(&g_a[cur][i]);
                    double dS1 = dan * dan * (double)s1fb;
                    double d = (it == 0)
                        ? dS1
                        : dS1 - 2.0 * dan * dao * (double)s2fb + sDS1[warp * 2 + 1];
                    sDS1[warp * 2 + 1] = dS1;
                    sRow[warp * 2 + 1] = d;
                }
            }
        }
        __syncthreads();
        if (tid == 0) {
            double s = 0.0;
            #pragma unroll
            for (int q = 0; q < 32; ++q) s += sRow[q];
            g_bdisp[blk] = s;
        }
        gbar(base + (++gen) * NB);

        if (warp == 0) {
            double sd = __ldcg(&g_bdisp[lane])      + __ldcg(&g_bdisp[lane + 32])
                      + __ldcg(&g_bdisp[lane + 64]) + __ldcg(&g_bdisp[lane + 96]);
            #pragma unroll
            for (int off = 16; off; off >>= 1)
                sd += __shfl_down_sync(FULL, sd, off);
            if (lane == 0) sDisp = sd;
        }
        __syncthreads();
        fpar = nxt;
        if (sDisp <= STOP_THR) break;
    }

    // ================= epilogue: P = a*K*b^T, C = -100*ln(K), cost ========
    // P/C rows at byte phase 4 (mod 16): aligned quads start at j=3+4q.
    __syncthreads();
    for (int i = tid; i < Mm; i += NT) sA[i] = __ldcg(&g_b[fpar][i]);
    __syncthreads();
    for (int m = tid; m < Mm - 3; m += NT) sB[m] = sA[m + 3];   // shifted copy
    __syncthreads();
    const float4* Bsh4 = (const float4*)sB;

    #pragma unroll
    for (int rr = 0; rr < 2; ++rr) {
        const int i = blk * 32 + warp * 2 + rr;
        const float ai = __ldcg(&g_a[fpar][i]);
        const float*  Kr = g_K + (size_t)i * Mm;
        const float4* K4 = (const float4*)Kr;
        float* Pr = Pout + (size_t)i * Mm;
        float* Cr = Cmat + (size_t)i * Mm;
        float csum = 0.f;

        if (lane < 3) {                  // head: j = 0,1,2
            float k = Kr[lane];
            float p = ai * k * sA[lane];
            float c = -69.31471805599453f * __log2f(k);
            __stcs(Pr + lane, p);
            __stcs(Cr + lane, c);
            csum = fmaf(p, c, csum);
        }

        float4 curr = K4[lane];
        for (int s = 0; s < 32; s++) {
            const int q = lane + 32 * s;
            const int nidx = (s < 31) ? (lane + 32 * (s + 1)) : lane;
            float4 newq = K4[nidx];
            float nx = __shfl_down_sync(FULL, curr.x, 1);
            float ny = __shfl_down_sync(FULL, curr.y, 1);
            float nz = __shfl_down_sync(FULL, curr.z, 1);
            float bx = __shfl_sync(FULL, newq.x, 0);
            float by = __shfl_sync(FULL, newq.y, 0);
            float bz = __shfl_sync(FULL, newq.z, 0);
            if (lane == 31) { nx = bx; ny = by; nz = bz; }

            if (q <= 1022) {
                const int jst = 4 * q + 3;
                float k0 = curr.w, k1 = nx, k2 = ny, k3 = nz;
                float4 bq = Bsh4[q];
                float p0 = ai * k0 * bq.x, p1 = ai * k1 * bq.y;
                float p2 = ai * k2 * bq.z, p3 = ai * k3 * bq.w;
                float c0 = -69.31471805599453f * __log2f(k0);
                float c1 = -69.31471805599453f * __log2f(k1);
                float c2 = -69.31471805599453f * __log2f(k2);
                float c3 = -69.31471805599453f * __log2f(k3);
                float4 pq; pq.x = p0; pq.y = p1; pq.z = p2; pq.w = p3;
                float4 cq; cq.x = c0; cq.y = c1; cq.z = c2; cq.w = c3;
                __stcs((float4*)(Pr + jst), pq);
                __stcs((float4*)(Cr + jst), cq);
                csum = fmaf(p0, c0, csum); csum = fmaf(p1, c1, csum);
                csum = fmaf(p2, c2, csum); csum = fmaf(p3, c3, csum);
            }
            if (s == 31 && lane == 31) {  // tail j = 4095
                float k = curr.w;
                float p = ai * k * sA[4095];
                float c = -69.31471805599453f * __log2f(k);
                __stcs(Pr + 4095, p);
                __stcs(Cr + 4095, c);
                csum = fmaf(p, c, csum);
            }
            curr = newq;
        }

        #pragma unroll
        for (int off = 16; off; off >>= 1)
            csum += __shfl_down_sync(FULL, csum, off);
        if (lane == 0) sRow[warp * 2 + rr] = (double)csum;
    }
    __syncthreads();
    if (tid == 0) {
        double s = 0.0;
        #pragma unroll
        for (int q = 0; q < 32; ++q) s += sRow[q];
        g_bcost[blk] = s;
    }
    gbar(base + (++gen) * NB);
    if (blk == 0 && warp == 0) {
        double sc = __ldcg(&g_bcost[lane])      + __ldcg(&g_bcost[lane + 32])
                  + __ldcg(&g_bcost[lane + 64]) + __ldcg(&g_bcost[lane + 96]);
        #pragma unroll
        for (int off = 16; off; off >>= 1)
            sc += __shfl_down_sync(FULL, sc, off);
        if (lane == 0) out[0] = (float)sc;
    }
}

// ---------------- launch ----------------
extern "C" void kernel_launch(void* const* d_in, const int* in_sizes, int n_in,
                              void* d_out, int out_size) {
    const float* x  = (const float*)d_in[0];   // [4096,64]
    const float* y  = (const float*)d_in[1];   // [4096,64]
    const float* mu = (const float*)d_in[2];   // [4096]
    const float* nu = (const float*)d_in[3];   // [4096]
    float* out = (float*)d_out;                // [1 + N*M + N*M] = cost | P | C

    const int smem = (128 * S2 + 64 * S2 + 128 + 64) * (int)sizeof(float);
    cudaFuncSetAttribute(fused_kernel, cudaFuncAttributeMaxDynamicSharedMemorySize, smem);
    fused_kernel<<<NB, NT, smem>>>(x, y, mu, nu, out);
}

// round 11
// speedup vs baseline: 1.3873x; 1.1354x over previous
#include <cuda_runtime.h>
#include <math.h>
#include <stdint.h>

#define Nn 4096
#define Mm 4096
#define LAMDA 0.01f
#define STOP_THR 1e-7
#define MAX_ITER 100
#define NB 128
#define NT 512
#define NW 16
#define S2 70   // smem row stride (floats), even (8B smem accesses)

typedef unsigned long long ull;

// ---------------- device globals ----------------
__device__ float  g_K[(size_t)Nn * Mm];   // 64 MB fp32 kernel matrix
__device__ float  g_a[2][Nn];
__device__ float  g_b[2][Mm];
__device__ double g_bdisp[NB];
__device__ double g_bcost[NB];
__device__ int    g_final;
__device__ unsigned g_bar_cnt;            // monotonic arrive counter

// ---------------- fast exp: FFMA-only ----------------
__device__ __forceinline__ float fexp(float xx) {
    float t  = fmaf(xx, 1.4426950408889634f, 12582912.0f);
    int   n  = __float_as_int(t) - 0x4B400000;
    float fn = t - 12582912.0f;
    float r  = fmaf(fn, -0.693145751953125f, xx);
    r        = fmaf(fn, -1.42860677e-6f, r);
    float p  = 1.3888890e-3f;
    p = fmaf(p, r, 8.3333338e-3f);
    p = fmaf(p, r, 4.1666668e-2f);
    p = fmaf(p, r, 1.6666667e-1f);
    p = fmaf(p, r, 5.0000000e-1f);
    p = fmaf(p, r, 1.0f);
    p = fmaf(p, r, 1.0f);
    return __int_as_float(__float_as_int(p) + (n << 23));
}

#define FMA2(d, a, b) \
    asm("fma.rn.f32x2 %0, %1, %2, %0;" : "+l"(d) : "l"(a), "l"(b))
#define MUL2(d, a, b) \
    asm("mul.rn.f32x2 %0, %1, %2;" : "=l"(d) : "l"(a), "l"(b))
#define UNPACK2(lo, hi, v) \
    asm("mov.b64 {%0, %1}, %2;" : "=f"(lo), "=f"(hi) : "l"(v))

// ------------- cheap acquire/release grid barrier -------
__device__ __forceinline__ void red_rel_add1(unsigned* p) {
    asm volatile("red.release.gpu.global.add.u32 [%0], 1;" :: "l"(p) : "memory");
}
__device__ __forceinline__ unsigned ld_acq(unsigned* p) {
    unsigned v;
    asm volatile("ld.acquire.gpu.global.u32 %0, [%1];" : "=r"(v) : "l"(p) : "memory");
    return v;
}
__device__ __forceinline__ void gbar(unsigned target) {
    __syncthreads();
    if (threadIdx.x == 0) {
        red_rel_add1(&g_bar_cnt);
        while ((int)(ld_acq(&g_bar_cnt) - target) < 0) { }
    }
    __syncthreads();
}

// ===================== Kernel 1: CK build =====================
// 128x128 tiles, 8 per block.  Per-thread 8 rows x 4 cols.
// xp loads are warp-broadcast; only K stored (C = -100 ln K later).
__global__ void __launch_bounds__(NT, 1)
ck_kernel(const float* __restrict__ x, const float* __restrict__ y) {
    extern __shared__ float sm[];
    float* XS = sm;                 // [128][S2]
    float* YS = sm + 128 * S2;      // [128][S2]
    float* xn = YS + 128 * S2;      // [128]
    float* yn = xn + 128;           // [128]

    const int tid = threadIdx.x, blk = blockIdx.x;
    const int lane = tid & 31, warp = tid >> 5;

    if (tid < 32) {                 // init iterate vectors
        g_a[0][blk * 32 + tid] = 1.0f / (float)Nn;
        g_b[0][blk * 32 + tid] = 1.0f;
    }

    const int i0 = (blk >> 2) * 128;
    for (int t = tid; t < 4096; t += NT) {
        int r = t >> 5, c = t & 31;
        float2 v = __ldg((const float2*)(x + (size_t)(i0 + r) * 64) + c);
        *(float2*)(XS + r * S2 + 2 * c) = v;
    }
    __syncthreads();
    if (tid < 128) {
        float s = 0.f;
        #pragma unroll
        for (int k = 0; k < 64; k++) { float v = XS[tid * S2 + k]; s = fmaf(v, v, s); }
        xn[tid] = s;
    }

    const int iy = warp * 8;        // 16 warps x 8 rows = 128
    for (int s = 0; s < 8; s++) {
        const int j0 = ((blk & 3) * 8 + s) * 128;
        __syncthreads();
        for (int t = tid; t < 4096; t += NT) {
            int r = t >> 5, c = t & 31;
            float2 v = __ldg((const float2*)(y + (size_t)(j0 + r) * 64) + c);
            *(float2*)(YS + r * S2 + 2 * c) = v;
        }
        __syncthreads();
        if (tid < 128) {
            float sv = 0.f;
            #pragma unroll
            for (int k = 0; k < 64; k++) { float v = YS[tid * S2 + k]; sv = fmaf(v, v, sv); }
            yn[tid] = sv;
        }
        __syncthreads();

        ull acc[8][4];
        #pragma unroll
        for (int u = 0; u < 8; u++)
            #pragma unroll
            for (int w = 0; w < 4; w++) acc[u][w] = 0ULL;

        #pragma unroll 2
        for (int kp = 0; kp < 32; kp++) {
            const int k = kp * 2;
            ull xp[8], yp[4];
            #pragma unroll
            for (int u = 0; u < 8; u++)
                xp[u] = *(const ull*)(XS + (iy + u) * S2 + k);   // warp-broadcast
            #pragma unroll
            for (int w = 0; w < 4; w++)
                yp[w] = *(const ull*)(YS + (lane + 32 * w) * S2 + k);
            #pragma unroll
            for (int u = 0; u < 8; u++)
                #pragma unroll
                for (int w = 0; w < 4; w++)
                    FMA2(acc[u][w], xp[u], yp[w]);
        }

        #pragma unroll
        for (int u = 0; u < 8; u++) {
            const int i = i0 + iy + u;
            const float xni = xn[iy + u];
            #pragma unroll
            for (int w = 0; w < 4; w++) {
                const int jl = lane + 32 * w;
                float lo, hi;
                UNPACK2(lo, hi, acc[u][w]);
                float Cv = xni + yn[jl] - 2.0f * (lo + hi);
                g_K[(size_t)i * Mm + j0 + jl] = fexp(-LAMDA * Cv);
            }
        }
    }
}

// ===================== Kernel 2: Sinkhorn loop =====================
__global__ void __launch_bounds__(NT, 1)
sink_kernel(const float* __restrict__ mu, const float* __restrict__ nu) {
    __shared__ float  sA[Nn];
    __shared__ float  sB[Mm];
    __shared__ float  sred[NW][33];
    __shared__ double sRow[32];
    __shared__ double sDS1[32];
    __shared__ double sDisp;

    const int tid = threadIdx.x, blk = blockIdx.x;
    const int warp = tid >> 5, lane = tid & 31;
    const unsigned FULL = 0xffffffffu;
    const unsigned base = __ldcg(&g_bar_cnt);
    unsigned gen = 0;
    int fpar = 0;

    for (int it = 0; it < MAX_ITER; ++it) {
        const int cur = it & 1, nxt = cur ^ 1;

        // ---- deferred convergence check on iteration it-1 (uses existing barrier)
        if (it > 0) {
            if (warp == 0) {
                double sd = __ldcg(&g_bdisp[lane])      + __ldcg(&g_bdisp[lane + 32])
                          + __ldcg(&g_bdisp[lane + 64]) + __ldcg(&g_bdisp[lane + 96]);
                #pragma unroll
                for (int off = 16; off; off >>= 1)
                    sd += __shfl_down_sync(FULL, sd, off);
                if (lane == 0) sDisp = sd;
            }
            __syncthreads();
            if (sDisp <= STOP_THR) { fpar = cur; break; }
            __syncthreads();
        }

        // ---- Phase A: b[nxt] = nu / (K^T a[cur])
        for (int i = tid; i < Nn; i += NT) sA[i] = __ldcg(&g_a[cur][i]);
        __syncthreads();
        {
            const int j = blk * 32 + lane;
            const float* Kc = g_K + j;
            float acc[16];
            #pragma unroll
            for (int u = 0; u < 16; u++) acc[u] = 0.f;
            for (int ib = 0; ib < Nn; ib += 256) {
                #pragma unroll
                for (int u = 0; u < 16; u++) {
                    const int i = ib + warp + 16 * u;
                    acc[u] = fmaf(Kc[(size_t)i * Mm], sA[i], acc[u]);
                }
            }
            float s0 = ((acc[0] + acc[1])   + (acc[2] + acc[3]))
                     + ((acc[4] + acc[5])   + (acc[6] + acc[7]));
            float s1 = ((acc[8] + acc[9])   + (acc[10] + acc[11]))
                     + ((acc[12] + acc[13]) + (acc[14] + acc[15]));
            sred[warp][lane] = s0 + s1;
        }
        __syncthreads();
        if (warp == 0) {
            float s = 0.f;
            #pragma unroll
            for (int w = 0; w < NW; ++w) s += sred[w][lane];
            int j = blk * 32 + lane;
            g_b[nxt][j] = __ldg(&nu[j]) / s;
        }
        gbar(base + (++gen) * NB);

        // ---- Phase B: a[nxt] = mu/(K b_new) + fused disp partials (2 rows interleaved)
        for (int i = tid; i < Mm; i += NT) sA[i] = __ldcg(&g_b[nxt][i]);
        for (int i = tid; i < Mm; i += NT) sB[i] = __ldcg(&g_b[cur][i]);
        __syncthreads();
        {
            const int i0r = blk * 32 + warp * 2;
            const ull* K2a = (const ull*)(g_K + (size_t)i0r * Mm);
            const ull* K2b = (const ull*)(g_K + (size_t)(i0r + 1) * Mm);
            const ull* A2 = (const ull*)sA;
            const ull* B2 = (const ull*)sB;
            ull ta = 0ULL, s1a = 0ULL, s2a = 0ULL;
            ull tb = 0ULL, s1b = 0ULL, s2b = 0ULL;
            #pragma unroll 4
            for (int j = lane; j < Mm / 2; j += 32) {
                ull ka = K2a[j], kb = K2b[j];
                ull bn = A2[j], be = B2[j];
                ull k2, tmp;
                MUL2(k2, ka, ka);
                FMA2(ta, ka, bn);
                MUL2(tmp, k2, bn);
                FMA2(s1a, tmp, bn);
                FMA2(s2a, tmp, be);
                MUL2(k2, kb, kb);
                FMA2(tb, kb, bn);
                MUL2(tmp, k2, bn);
                FMA2(s1b, tmp, bn);
                FMA2(s2b, tmp, be);
            }
            float l, h;
            UNPACK2(l, h, ta);  float tfa = l + h;
            UNPACK2(l, h, s1a); float s1fa = l + h;
            UNPACK2(l, h, s2a); float s2fa = l + h;
            UNPACK2(l, h, tb);  float tfb = l + h;
            UNPACK2(l, h, s1b); float s1fb = l + h;
            UNPACK2(l, h, s2b); float s2fb = l + h;
            #pragma unroll
            for (int off = 16; off; off >>= 1) {
                tfa  += __shfl_down_sync(FULL, tfa,  off);
                s1fa += __shfl_down_sync(FULL, s1fa, off);
                s2fa += __shfl_down_sync(FULL, s2fa, off);
                tfb  += __shfl_down_sync(FULL, tfb,  off);
                s1fb += __shfl_down_sync(FULL, s1fb, off);
                s2fb += __shfl_down_sync(FULL, s2fb, off);
            }
            if (lane == 0) {
                {
                    const int i = i0r;
                    float an = __ldg(&mu[i]) / tfa;
                    g_a[nxt][i] = an;
                    double dan = (double)an;
                    double dao = (double)__ldcg(&g_a[cur][i]);
                    double dS1 = dan * dan * (double)s1fa;
                    double d = (it == 0)
                        ? dS1
                        : dS1 - 2.0 * dan * dao * (double)s2fa + sDS1[warp * 2];
                    sDS1[warp * 2] = dS1;
                    sRow[warp * 2] = d;
                }
                {
                    const int i = i0r + 1;
                    float an = __ldg(&mu[i]) / tfb;
                    g_a[nxt][i] = an;
                    double dan = (double)an;
                    double dao = (double)__ldcg(&g_a[cur][i]);
                    double dS1 = dan * dan * (double)s1fb;
                    double d = (it == 0)
                        ? dS1
                        : dS1 - 2.0 * dan * dao * (double)s2fb + sDS1[warp * 2 + 1];
                    sDS1[warp * 2 + 1] = dS1;
                    sRow[warp * 2 + 1] = d;
                }
            }
        }
        __syncthreads();
        if (tid == 0) {
            double s = 0.0;
            #pragma unroll
            for (int q = 0; q < 32; ++q) s += sRow[q];
            g_bdisp[blk] = s;
        }
        fpar = nxt;
        gbar(base + (++gen) * NB);
    }

    if (blk == 0 && tid == 0) g_final = fpar;
}

// ===================== Kernel 3: epilogue =====================
// P = a*K*b^T, C = -100*ln(K), per-block cost partial.
__global__ void __launch_bounds__(NT, 1)
epi_kernel(float* __restrict__ out) {
    __shared__ float  sA[Mm];
    __shared__ float  sB[Mm];
    __shared__ double sRow[32];

    const int tid = threadIdx.x, blk = blockIdx.x;
    const int warp = tid >> 5, lane = tid & 31;
    const unsigned FULL = 0xffffffffu;
    const int fpar = __ldcg(&g_final);

    float* Pout = out + 1;
    float* Cmat = out + 1 + (size_t)Nn * Mm;

    for (int i = tid; i < Mm; i += NT) sA[i] = __ldcg(&g_b[fpar][i]);
    __syncthreads();
    for (int m = tid; m < Mm - 3; m += NT) sB[m] = sA[m + 3];
    __syncthreads();
    const float4* Bsh4 = (const float4*)sB;

    #pragma unroll
    for (int rr = 0; rr < 2; ++rr) {
        const int i = blk * 32 + warp * 2 + rr;
        const float ai = __ldcg(&g_a[fpar][i]);
        const float*  Kr = g_K + (size_t)i * Mm;
        const float4* K4 = (const float4*)Kr;
        float* Pr = Pout + (size_t)i * Mm;
        float* Cr = Cmat + (size_t)i * Mm;
        float csum = 0.f;

        if (lane < 3) {                  // head j = 0,1,2
            float k = Kr[lane];
            float p = ai * k * sA[lane];
            float c = -69.31471805599453f * __log2f(k);
            __stcs(Pr + lane, p);
            __stcs(Cr + lane, c);
            csum = fmaf(p, c, csum);
        }

        float4 curr = K4[lane];
        for (int s = 0; s < 32; s++) {
            const int q = lane + 32 * s;
            const int nidx = (s < 31) ? (lane + 32 * (s + 1)) : lane;
            float4 newq = K4[nidx];
            float nx = __shfl_down_sync(FULL, curr.x, 1);
            float ny = __shfl_down_sync(FULL, curr.y, 1);
            float nz = __shfl_down_sync(FULL, curr.z, 1);
            float bx = __shfl_sync(FULL, newq.x, 0);
            float by = __shfl_sync(FULL, newq.y, 0);
            float bz = __shfl_sync(FULL, newq.z, 0);
            if (lane == 31) { nx = bx; ny = by; nz = bz; }

            if (q <= 1022) {
                const int jst = 4 * q + 3;
                float k0 = curr.w, k1 = nx, k2 = ny, k3 = nz;
                float4 bq = Bsh4[q];
                float p0 = ai * k0 * bq.x, p1 = ai * k1 * bq.y;
                float p2 = ai * k2 * bq.z, p3 = ai * k3 * bq.w;
                float c0 = -69.31471805599453f * __log2f(k0);
                float c1 = -69.31471805599453f * __log2f(k1);
                float c2 = -69.31471805599453f * __log2f(k2);
                float c3 = -69.31471805599453f * __log2f(k3);
                float4 pq; pq.x = p0; pq.y = p1; pq.z = p2; pq.w = p3;
                float4 cq; cq.x = c0; cq.y = c1; cq.z = c2; cq.w = c3;
                __stcs((float4*)(Pr + jst), pq);
                __stcs((float4*)(Cr + jst), cq);
                csum = fmaf(p0, c0, csum); csum = fmaf(p1, c1, csum);
                csum = fmaf(p2, c2, csum); csum = fmaf(p3, c3, csum);
            }
            if (s == 31 && lane == 31) {  // tail j = 4095
                float k = curr.w;
                float p = ai * k * sA[4095];
                float c = -69.31471805599453f * __log2f(k);
                __stcs(Pr + 4095, p);
                __stcs(Cr + 4095, c);
                csum = fmaf(p, c, csum);
            }
            curr = newq;
        }

        #pragma unroll
        for (int off = 16; off; off >>= 1)
            csum += __shfl_down_sync(FULL, csum, off);
        if (lane == 0) sRow[warp * 2 + rr] = (double)csum;
    }
    __syncthreads();
    if (tid == 0) {
        double s = 0.0;
        #pragma unroll
        for (int q = 0; q < 32; ++q) s += sRow[q];
        g_bcost[blk] = s;
    }
}

// ===================== Kernel 4: cost reduce =====================
__global__ void cost_kernel(float* __restrict__ out) {
    __shared__ double sdd[128];
    const int tid = threadIdx.x;
    sdd[tid] = __ldcg(&g_bcost[tid]);
    __syncthreads();
    for (int off = 64; off; off >>= 1) {
        if (tid < off) sdd[tid] += sdd[tid + off];
        __syncthreads();
    }
    if (tid == 0) out[0] = (float)sdd[0];
}

// ---------------- launch ----------------
extern "C" void kernel_launch(void* const* d_in, const int* in_sizes, int n_in,
                              void* d_out, int out_size) {
    const float* x  = (const float*)d_in[0];
    const float* y  = (const float*)d_in[1];
    const float* mu = (const float*)d_in[2];
    const float* nu = (const float*)d_in[3];
    float* out = (float*)d_out;

    const int ck_smem = (256 * S2 + 256) * (int)sizeof(float);
    cudaFuncSetAttribute(ck_kernel, cudaFuncAttributeMaxDynamicSharedMemorySize, ck_smem);

    ck_kernel<<<NB, NT, ck_smem>>>(x, y);
    sink_kernel<<<NB, NT>>>(mu, nu);
    epi_kernel<<<NB, NT>>>(out);
    cost_kernel<<<1, 128>>>(out);
}